// round 2
// baseline (speedup 1.0000x reference)
#include <cuda_runtime.h>
#include <cstdint>

// ---------------------------------------------------------------------------
// DensityMatrixMLP fused kernel, fp32, f32x2 packed FMA (sm_103a).
//   per CTA: 128 batch rows.
//   stage 1: H = relu(X[128,256] @ W1[256,128] + b1)         -> smem Hs
//   stage 2: V = H @ W2[128,136] + b2                        -> smem Vs
//            trace = ||V||^2 per row (tr(L L^T) = sum v^2)   -> smem tr
//   stage 3: rho[i][j] = (1/trace) * sum_k L[i,k] L[j,k]     -> gmem
// ---------------------------------------------------------------------------

#define BATCH_ROWS   128          // rows per CTA
#define IN_DIM       256
#define HID          128
#define TRIL         136
#define N2PAD        160          // GEMM2 N padded (zero cols 136..159)
#define THREADS      256
#define KC           32           // k-chunk for GEMM1

// smem layout (bytes)
#define HS_STRIDE    129                       // Hs[128][129] floats
#define OFF_HS       0
#define SZ_HS        (128 * HS_STRIDE * 4)     // 66048
#define OFF_W2       (OFF_HS + SZ_HS)          // 66048
#define SZ_W2        (128 * N2PAD * 4)         // 81920
#define OFF_V        (OFF_W2 + SZ_W2)          // 147968
#define VS_STRIDE    137
#define SZ_V         (128 * VS_STRIDE * 4)     // 70144
#define OFF_TR       (OFF_V + SZ_V)            // 218112
#define SMEM_BYTES   (OFF_TR + 128 * 4)        // 218624
// stage-1 scratch overlays the Vs region:
#define OFF_XS       OFF_V                     // Xs[128][33] floats (16896 B)
#define XS_STRIDE    33
#define OFF_W1S      (OFF_V + 128 * XS_STRIDE * 4)  // W1s[32][128] (16384 B)

__device__ __forceinline__ float2 ffma2(float2 a, float2 b, float2 c) {
    union U { float2 f; unsigned long long u; };
    U A, Bv, C, D;
    A.f = a; Bv.f = b; C.f = c;
    asm("fma.rn.f32x2 %0, %1, %2, %3;"
        : "=l"(D.u) : "l"(A.u), "l"(Bv.u), "l"(C.u));
    return D.f;
}

// stage-3 helper: compile-time row index I of L; computes one row of rho.
template <int I>
__device__ __forceinline__ void rho_row(const float* __restrict__ vrow,
                                        float invtr,
                                        float* __restrict__ orow) {
    constexpr int TI = I * (I + 1) / 2;
    float Li[I + 1];
#pragma unroll
    for (int k = 0; k <= I; k++) Li[k] = vrow[TI + k];
    float res[16];
#pragma unroll
    for (int j = 0; j < 16; j++) {
        const int tj  = j * (j + 1) / 2;
        const int len = (j < I) ? j : I;
        float dot = 0.f;
#pragma unroll
        for (int k = 0; k <= len; k++) dot = fmaf(Li[k], vrow[tj + k], dot);
        res[j] = dot * invtr;
    }
#pragma unroll
    for (int q = 0; q < 4; q++) {
        float4 o = make_float4(res[4 * q], res[4 * q + 1],
                               res[4 * q + 2], res[4 * q + 3]);
        *reinterpret_cast<float4*>(&orow[I * 16 + 4 * q]) = o;
    }
}

__global__ void __launch_bounds__(THREADS, 1)
density_mlp_kernel(const float* __restrict__ x,
                   const float* __restrict__ W1,
                   const float* __restrict__ b1,
                   const float* __restrict__ W2,
                   const float* __restrict__ b2,
                   float* __restrict__ out) {
    extern __shared__ char smem[];
    float* Hs  = reinterpret_cast<float*>(smem + OFF_HS);   // [128][129]
    float* W2s = reinterpret_cast<float*>(smem + OFF_W2);   // [128][160]
    float* Vs  = reinterpret_cast<float*>(smem + OFF_V);    // [128][137]
    float* tr  = reinterpret_cast<float*>(smem + OFF_TR);   // [128]
    float* Xs  = reinterpret_cast<float*>(smem + OFF_XS);   // [128][33]
    float* W1s = reinterpret_cast<float*>(smem + OFF_W1S);  // [32][128]

    const int tid       = threadIdx.x;
    const int block_row = blockIdx.x * BATCH_ROWS;

    // ---- preload W2 (padded with zeros to N2PAD cols), zero trace buffer ----
    for (int e = tid; e < 128 * N2PAD; e += THREADS) {
        int k = e / N2PAD, n = e - k * N2PAD;
        W2s[e] = (n < TRIL) ? W2[k * TRIL + n] : 0.f;
    }
    if (tid < 128) tr[tid] = 0.f;

    // ======================= stage 1: H = relu(X@W1+b1) ======================
    // thread tile: 8 rows x 8 cols. tx in [0,16) cols, ty in [0,16) rows.
    {
        const int tx = tid & 15, ty = tid >> 4;
        const int m0 = ty * 8, n0 = tx * 8;

        float2 c1[8][4];
#pragma unroll
        for (int p = 0; p < 4; p++) {
            float bx = b1[n0 + 2 * p], by = b1[n0 + 2 * p + 1];
#pragma unroll
            for (int i = 0; i < 8; i++) c1[i][p] = make_float2(bx, by);
        }

        for (int kc = 0; kc < IN_DIM; kc += KC) {
            __syncthreads();
            // load X tile [128 rows x 32 k], store transpose-free as Xs[m][k]
#pragma unroll
            for (int c = 0; c < 4; c++) {
                int v   = tid + THREADS * c;          // 0..1023 float4s
                int row = v >> 3, kq = (v & 7) * 4;
                float4 xv = *reinterpret_cast<const float4*>(
                    &x[(size_t)(block_row + row) * IN_DIM + kc + kq]);
                float* d = &Xs[row * XS_STRIDE + kq];
                d[0] = xv.x; d[1] = xv.y; d[2] = xv.z; d[3] = xv.w;
            }
            // load W1 tile [32 k x 128 n]
#pragma unroll
            for (int c = 0; c < 4; c++) {
                int v  = tid + THREADS * c;
                int kr = v >> 5, col = (v & 31) * 4;
                *reinterpret_cast<float4*>(&W1s[kr * HID + col]) =
                    *reinterpret_cast<const float4*>(&W1[(size_t)(kc + kr) * HID + col]);
            }
            __syncthreads();

#pragma unroll 8
            for (int k = 0; k < KC; k++) {
                float a[8];
#pragma unroll
                for (int i = 0; i < 8; i++) a[i] = Xs[(m0 + i) * XS_STRIDE + k];
                float4 bA = *reinterpret_cast<const float4*>(&W1s[k * HID + n0]);
                float4 bB = *reinterpret_cast<const float4*>(&W1s[k * HID + n0 + 4]);
                float2 bv[4] = { make_float2(bA.x, bA.y), make_float2(bA.z, bA.w),
                                 make_float2(bB.x, bB.y), make_float2(bB.z, bB.w) };
#pragma unroll
                for (int i = 0; i < 8; i++) {
                    float2 ai = make_float2(a[i], a[i]);
#pragma unroll
                    for (int p = 0; p < 4; p++) c1[i][p] = ffma2(ai, bv[p], c1[i][p]);
                }
            }
        }
        __syncthreads();
        // relu + store Hs
#pragma unroll
        for (int i = 0; i < 8; i++) {
            float* h = &Hs[(m0 + i) * HS_STRIDE + n0];
#pragma unroll
            for (int p = 0; p < 4; p++) {
                h[2 * p]     = fmaxf(c1[i][p].x, 0.f);
                h[2 * p + 1] = fmaxf(c1[i][p].y, 0.f);
            }
        }
    }
    __syncthreads();

    // ======================= stage 2: V = H@W2+b2, trace =====================
    // thread tile: 8 rows x 10 cols (5 float2). N padded to 160.
    {
        const int tx = tid & 15, ty = tid >> 4;
        const int m0 = ty * 8, n0 = tx * 10;

        float2 c2[8][5];
#pragma unroll
        for (int p = 0; p < 5; p++) {
            int n = n0 + 2 * p;
            float bx = (n < TRIL)     ? b2[n]     : 0.f;
            float by = (n + 1 < TRIL) ? b2[n + 1] : 0.f;
#pragma unroll
            for (int i = 0; i < 8; i++) c2[i][p] = make_float2(bx, by);
        }

#pragma unroll 4
        for (int k = 0; k < HID; k++) {
            float h[8];
#pragma unroll
            for (int i = 0; i < 8; i++) h[i] = Hs[(m0 + i) * HS_STRIDE + k];
            float2 w[5];
#pragma unroll
            for (int p = 0; p < 5; p++)
                w[p] = *reinterpret_cast<const float2*>(&W2s[k * N2PAD + n0 + 2 * p]);
#pragma unroll
            for (int i = 0; i < 8; i++) {
                float2 hi = make_float2(h[i], h[i]);
#pragma unroll
                for (int p = 0; p < 5; p++) c2[i][p] = ffma2(hi, w[p], c2[i][p]);
            }
        }

        // write V (cols < 136) and accumulate trace partials
#pragma unroll
        for (int i = 0; i < 8; i++) {
            float part = 0.f;
            float* vr = &Vs[(m0 + i) * VS_STRIDE];
#pragma unroll
            for (int p = 0; p < 5; p++) {
                float2 v = c2[i][p];
                int n = n0 + 2 * p;
                if (n < TRIL)     vr[n]     = v.x;
                if (n + 1 < TRIL) vr[n + 1] = v.y;
                part = fmaf(v.x, v.x, fmaf(v.y, v.y, part));  // padded cols are 0
            }
            atomicAdd(&tr[m0 + i], part);
        }
    }
    __syncthreads();

    // ======================= stage 3: rho = L L^T / trace ====================
    {
        const int row = tid & 127;
        const int ib  = tid >> 7;                 // warps 0-3: even i, 4-7: odd i
        const float* vrow = &Vs[row * VS_STRIDE];
        const float invtr = 1.0f / tr[row];
        float* orow = &out[(size_t)(block_row + row) * 256];
        if (ib == 0) {
            rho_row<0>(vrow, invtr, orow);  rho_row<2>(vrow, invtr, orow);
            rho_row<4>(vrow, invtr, orow);  rho_row<6>(vrow, invtr, orow);
            rho_row<8>(vrow, invtr, orow);  rho_row<10>(vrow, invtr, orow);
            rho_row<12>(vrow, invtr, orow); rho_row<14>(vrow, invtr, orow);
        } else {
            rho_row<1>(vrow, invtr, orow);  rho_row<3>(vrow, invtr, orow);
            rho_row<5>(vrow, invtr, orow);  rho_row<7>(vrow, invtr, orow);
            rho_row<9>(vrow, invtr, orow);  rho_row<11>(vrow, invtr, orow);
            rho_row<13>(vrow, invtr, orow); rho_row<15>(vrow, invtr, orow);
        }
    }
}

extern "C" void kernel_launch(void* const* d_in, const int* in_sizes, int n_in,
                              void* d_out, int out_size) {
    const float* x  = (const float*)d_in[0];
    const float* W1 = (const float*)d_in[1];
    const float* b1 = (const float*)d_in[2];
    const float* W2 = (const float*)d_in[3];
    const float* b2 = (const float*)d_in[4];
    float* out = (float*)d_out;

    const int batch  = in_sizes[0] / IN_DIM;      // 131072
    const int blocks = batch / BATCH_ROWS;        // 1024

    cudaFuncSetAttribute(density_mlp_kernel,
                         cudaFuncAttributeMaxDynamicSharedMemorySize, SMEM_BYTES);
    density_mlp_kernel<<<blocks, THREADS, SMEM_BYTES>>>(x, W1, b1, W2, b2, out);
}

// round 4
// speedup vs baseline: 2.2630x; 2.2630x over previous
#include <cuda_runtime.h>
#include <cuda_bf16.h>
#include <cstdint>

// ===========================================================================
// DensityMatrixMLP, fused, bf16 split-precision mma.sync (HMMA path).
// compute_103-safe: no tcgen05/TMEM (arch-specific features unavailable
// through the harness's virtual arch).
//
// Per CTA (128 batch rows, 8 warps):
//   GEMM1: C1[128,128] = X[128,256] @ W1, 3-term bf16 split, fp32 acc
//   epi1 : H = relu(C1 + b1) -> bf16 hi/lo smem (k-contig rows)
//   GEMM2: C2[128,144] = H @ W2 (n padded 136->144 with zeros)
//   epi2 : V = C2 + b2 -> smem Vs; trace = sum V^2 per row (smem atomics)
//   rho  : L L^T / trace -> gmem
// ===========================================================================

#define THREADS 256
#define TRIL    136
#define VS_STRIDE 137

// ---- smem layout (bytes) ----
#define OFF_B1   0            // 128 f32
#define OFF_B2   512          // 136 f32
#define OFF_TR   1088         // 128 f32
#define OFF_A    2048         // 64 KB region
#define XHI      (OFF_A)              // 128r x 256B (128 k bf16)
#define XLO      (OFF_A + 32768)
#define HHI      (OFF_A)              // overlay after GEMM1
#define HLO      (OFF_A + 32768)
#define OFF_VS   (OFF_A)              // overlay after GEMM2 (70144 B)
#define OFF_B    (OFF_A + 65536)      // 80 KB region
#define W1HI     (OFF_B)              // 128k x 256B (128 n bf16)
#define W1LO     (OFF_B + 32768)
#define W2HI     (OFF_B)              // overlay: 128k x 320B (144 n bf16)
#define W2LO     (OFF_B + 40960)
#define SMEM_BYTES (OFF_B + 81920)    // 149504

static __device__ __forceinline__ uint32_t smem_u32(const void* p) {
    uint32_t a;
    asm("{ .reg .u64 t; cvta.to.shared.u64 t, %1; cvt.u32.u64 %0, t; }"
        : "=r"(a) : "l"(p));
    return a;
}

// XOR swizzle, 256B row stride (16 chunks of 16B)
static __device__ __forceinline__ uint32_t swz256(int row, int bc) {
    return (uint32_t)(row * 256 + ((((bc >> 4) ^ (row & 7)) << 4) | (bc & 15)));
}
// 320B row stride (18 chunks used; only chunks 0..15 swizzled)
static __device__ __forceinline__ uint32_t swz320(int row, int bc) {
    int c = bc >> 4;
    if (c < 16) c ^= (row & 7);
    return (uint32_t)(row * 320 + (c << 4) + (bc & 15));
}
// ldmatrix per-lane address, 256B-stride tiles
static __device__ __forceinline__ uint32_t lm256(uint32_t base, int r0, int bc0, int lane) {
    int row = r0 + (lane & 15);
    int bc  = bc0 + ((lane >> 4) << 4);
    return base + swz256(row, bc);
}
static __device__ __forceinline__ uint32_t lm320(uint32_t base, int r0, int bc0, int lane) {
    int row = r0 + (lane & 15);
    int bc  = bc0 + ((lane >> 4) << 4);
    return base + swz320(row, bc);
}

static __device__ __forceinline__ void ldsm_x4(uint32_t a, uint32_t r[4]) {
    asm volatile("ldmatrix.sync.aligned.m8n8.x4.shared.b16 {%0,%1,%2,%3}, [%4];"
                 : "=r"(r[0]), "=r"(r[1]), "=r"(r[2]), "=r"(r[3]) : "r"(a));
}
static __device__ __forceinline__ void ldsm_x4t(uint32_t a, uint32_t r[4]) {
    asm volatile("ldmatrix.sync.aligned.m8n8.x4.trans.shared.b16 {%0,%1,%2,%3}, [%4];"
                 : "=r"(r[0]), "=r"(r[1]), "=r"(r[2]), "=r"(r[3]) : "r"(a));
}
static __device__ __forceinline__ void ldsm_x2t(uint32_t a, uint32_t r[2]) {
    asm volatile("ldmatrix.sync.aligned.m8n8.x2.trans.shared.b16 {%0,%1}, [%2];"
                 : "=r"(r[0]), "=r"(r[1]) : "r"(a));
}

static __device__ __forceinline__ void mma_bf16(float d[4], const uint32_t a[4],
                                                const uint32_t b[2]) {
    asm volatile(
        "mma.sync.aligned.m16n8k16.row.col.f32.bf16.bf16.f32 "
        "{%0,%1,%2,%3}, {%4,%5,%6,%7}, {%8,%9}, {%0,%1,%2,%3};"
        : "+f"(d[0]), "+f"(d[1]), "+f"(d[2]), "+f"(d[3])
        : "r"(a[0]), "r"(a[1]), "r"(a[2]), "r"(a[3]), "r"(b[0]), "r"(b[1]));
}

static __device__ __forceinline__ uint32_t bf2u(__nv_bfloat162 v) {
    return *reinterpret_cast<uint32_t*>(&v);
}

// split 8 fp32 -> 16B hi + 16B lo bf16
static __device__ __forceinline__ void split8(const float* v, uint4& h, uint4& l) {
    uint32_t hp[4], lp[4];
#pragma unroll
    for (int q = 0; q < 4; q++) {
        float a = v[2*q], b = v[2*q+1];
        __nv_bfloat162 hh = __floats2bfloat162_rn(a, b);
        float ra = a - __bfloat162float(__low2bfloat16(hh));
        float rb = b - __bfloat162float(__high2bfloat16(hh));
        __nv_bfloat162 ll = __floats2bfloat162_rn(ra, rb);
        hp[q] = bf2u(hh); lp[q] = bf2u(ll);
    }
    h = make_uint4(hp[0], hp[1], hp[2], hp[3]);
    l = make_uint4(lp[0], lp[1], lp[2], lp[3]);
}

// stage-3: one compile-time row of rho
template <int I>
static __device__ __forceinline__ void rho_row(const float* __restrict__ vrow,
                                               float invtr, float* __restrict__ orow) {
    constexpr int TI = I * (I + 1) / 2;
    float Li[I + 1];
#pragma unroll
    for (int k = 0; k <= I; k++) Li[k] = vrow[TI + k];
    float res[16];
#pragma unroll
    for (int j = 0; j < 16; j++) {
        const int tj = j * (j + 1) / 2;
        const int len = (j < I) ? j : I;
        float dot = 0.f;
#pragma unroll
        for (int k = 0; k <= len; k++) dot = fmaf(Li[k], vrow[tj + k], dot);
        res[j] = dot * invtr;
    }
#pragma unroll
    for (int q = 0; q < 4; q++)
        *reinterpret_cast<float4*>(&orow[I * 16 + 4 * q]) =
            make_float4(res[4*q], res[4*q+1], res[4*q+2], res[4*q+3]);
}

__global__ void __launch_bounds__(THREADS, 1)
density_mlp_hmma(const float* __restrict__ x,
                 const float* __restrict__ W1,
                 const float* __restrict__ b1,
                 const float* __restrict__ W2,
                 const float* __restrict__ b2,
                 float* __restrict__ out) {
    extern __shared__ char smem[];
    const uint32_t sb = smem_u32(smem);
    const int tid  = threadIdx.x;
    const int wid  = tid >> 5;
    const int lane = tid & 31;
    const int brow = blockIdx.x * 128;

    float* bias1 = reinterpret_cast<float*>(smem + OFF_B1);
    float* bias2 = reinterpret_cast<float*>(smem + OFF_B2);
    float* trc   = reinterpret_cast<float*>(smem + OFF_TR);

    if (tid < 128) { bias1[tid] = b1[tid]; trc[tid] = 0.f; }
    if (tid < TRIL) bias2[tid] = b2[tid];

    const int m0  = (wid >> 1) * 32;      // warp row base
    const int n0g = (wid & 1) * 64;       // warp col base (GEMM1)

    // ======================= GEMM1: 2 K-chunks of 128 =======================
    float acc[2][8][4];
#pragma unroll
    for (int mt = 0; mt < 2; mt++)
#pragma unroll
    for (int nt = 0; nt < 8; nt++)
#pragma unroll
    for (int q = 0; q < 4; q++) acc[mt][nt][q] = 0.f;

    for (int c = 0; c < 2; c++) {
        if (c) __syncthreads();           // warps done with previous chunk smem
        // X chunk [128r x 128k] -> XHI/XLO
#pragma unroll
        for (int i = 0; i < 8; i++) {
            int u = tid + i * THREADS;    // 0..2047
            int row = u >> 4, j = u & 15;
            const float* s = x + (size_t)(brow + row) * 256 + c * 128 + j * 8;
            float4 p = *reinterpret_cast<const float4*>(s);
            float4 q4 = *reinterpret_cast<const float4*>(s + 4);
            float v[8] = {p.x, p.y, p.z, p.w, q4.x, q4.y, q4.z, q4.w};
            uint4 h, l; split8(v, h, l);
            uint32_t off = swz256(row, j * 16);
            *reinterpret_cast<uint4*>(smem + XHI + off) = h;
            *reinterpret_cast<uint4*>(smem + XLO + off) = l;
        }
        // W1 chunk [128k x 128n] -> W1HI/W1LO (k-major rows, coalesced)
#pragma unroll
        for (int i = 0; i < 8; i++) {
            int u = tid + i * THREADS;
            int k = u >> 4, j = u & 15;
            const float* s = W1 + (size_t)(c * 128 + k) * 128 + j * 8;
            float4 p = *reinterpret_cast<const float4*>(s);
            float4 q4 = *reinterpret_cast<const float4*>(s + 4);
            float v[8] = {p.x, p.y, p.z, p.w, q4.x, q4.y, q4.z, q4.w};
            uint4 h, l; split8(v, h, l);
            uint32_t off = swz256(k, j * 16);
            *reinterpret_cast<uint4*>(smem + W1HI + off) = h;
            *reinterpret_cast<uint4*>(smem + W1LO + off) = l;
        }
        __syncthreads();

#pragma unroll
        for (int kt = 0; kt < 8; kt++) {
            uint32_t ah[2][4], al[2][4];
            ldsm_x4(lm256(sb + XHI, m0,      kt * 32, lane), ah[0]);
            ldsm_x4(lm256(sb + XHI, m0 + 16, kt * 32, lane), ah[1]);
            ldsm_x4(lm256(sb + XLO, m0,      kt * 32, lane), al[0]);
            ldsm_x4(lm256(sb + XLO, m0 + 16, kt * 32, lane), al[1]);
            uint32_t bh[8][2], bl[8][2];
#pragma unroll
            for (int p = 0; p < 4; p++) {
                uint32_t t[4];
                ldsm_x4t(lm256(sb + W1HI, kt * 16, (n0g + p * 16) * 2, lane), t);
                bh[2*p][0] = t[0]; bh[2*p][1] = t[1];
                bh[2*p+1][0] = t[2]; bh[2*p+1][1] = t[3];
                ldsm_x4t(lm256(sb + W1LO, kt * 16, (n0g + p * 16) * 2, lane), t);
                bl[2*p][0] = t[0]; bl[2*p][1] = t[1];
                bl[2*p+1][0] = t[2]; bl[2*p+1][1] = t[3];
            }
#pragma unroll
            for (int mt = 0; mt < 2; mt++)
#pragma unroll
            for (int nt = 0; nt < 8; nt++) {
                mma_bf16(acc[mt][nt], ah[mt], bh[nt]);
                mma_bf16(acc[mt][nt], ah[mt], bl[nt]);
                mma_bf16(acc[mt][nt], al[mt], bh[nt]);
            }
        }
    }
    __syncthreads();                      // GEMM1 done; A/B regions reusable

    // ============== epilogue 1: H = relu(C1+b1) -> HHI/HLO ==================
#pragma unroll
    for (int mt = 0; mt < 2; mt++)
#pragma unroll
    for (int nt = 0; nt < 8; nt++) {
        int col = n0g + nt * 8 + ((lane & 3) << 1);
        float ba = bias1[col], bb = bias1[col + 1];
        int r = m0 + mt * 16 + (lane >> 2);
#pragma unroll
        for (int half = 0; half < 2; half++) {
            float v0 = fmaxf(acc[mt][nt][2*half]     + ba, 0.f);
            float v1 = fmaxf(acc[mt][nt][2*half + 1] + bb, 0.f);
            __nv_bfloat162 hh = __floats2bfloat162_rn(v0, v1);
            float r0 = v0 - __bfloat162float(__low2bfloat16(hh));
            float r1 = v1 - __bfloat162float(__high2bfloat16(hh));
            __nv_bfloat162 ll = __floats2bfloat162_rn(r0, r1);
            uint32_t off = swz256(r + half * 8, col * 2);
            *reinterpret_cast<uint32_t*>(smem + HHI + off) = bf2u(hh);
            *reinterpret_cast<uint32_t*>(smem + HLO + off) = bf2u(ll);
        }
    }
    // W2 [128k x 136n] -> W2HI/W2LO, n padded to 144 (zeros)
#pragma unroll
    for (int i = 0; i < 9; i++) {
        int u = tid + i * THREADS;        // 0..2303
        int k = u / 18, j = u - k * 18;
        float v[8];
        if (j < 17) {
            const float* s = W2 + (size_t)k * TRIL + j * 8;
            float4 p = *reinterpret_cast<const float4*>(s);
            float4 q4 = *reinterpret_cast<const float4*>(s + 4);
            v[0]=p.x; v[1]=p.y; v[2]=p.z; v[3]=p.w;
            v[4]=q4.x; v[5]=q4.y; v[6]=q4.z; v[7]=q4.w;
        } else {
#pragma unroll
            for (int t = 0; t < 8; t++) v[t] = 0.f;
        }
        uint4 h, l; split8(v, h, l);
        uint32_t off = swz320(k, j * 16);
        *reinterpret_cast<uint4*>(smem + W2HI + off) = h;
        *reinterpret_cast<uint4*>(smem + W2LO + off) = l;
    }
    __syncthreads();

    // ========================== GEMM2: H @ W2 ===============================
    const int n0g2 = (wid & 1) * 72;
    float acc2[2][9][4];
#pragma unroll
    for (int mt = 0; mt < 2; mt++)
#pragma unroll
    for (int nt = 0; nt < 9; nt++)
#pragma unroll
    for (int q = 0; q < 4; q++) acc2[mt][nt][q] = 0.f;

#pragma unroll
    for (int kt = 0; kt < 8; kt++) {
        uint32_t ah[2][4], al[2][4];
        ldsm_x4(lm256(sb + HHI, m0,      kt * 32, lane), ah[0]);
        ldsm_x4(lm256(sb + HHI, m0 + 16, kt * 32, lane), ah[1]);
        ldsm_x4(lm256(sb + HLO, m0,      kt * 32, lane), al[0]);
        ldsm_x4(lm256(sb + HLO, m0 + 16, kt * 32, lane), al[1]);
        uint32_t bh[9][2], bl[9][2];
#pragma unroll
        for (int p = 0; p < 4; p++) {
            uint32_t t[4];
            ldsm_x4t(lm320(sb + W2HI, kt * 16, (n0g2 + p * 16) * 2, lane), t);
            bh[2*p][0] = t[0]; bh[2*p][1] = t[1];
            bh[2*p+1][0] = t[2]; bh[2*p+1][1] = t[3];
            ldsm_x4t(lm320(sb + W2LO, kt * 16, (n0g2 + p * 16) * 2, lane), t);
            bl[2*p][0] = t[0]; bl[2*p][1] = t[1];
            bl[2*p+1][0] = t[2]; bl[2*p+1][1] = t[3];
        }
        ldsm_x2t(lm320(sb + W2HI, kt * 16, (n0g2 + 64) * 2, lane), bh[8]);
        ldsm_x2t(lm320(sb + W2LO, kt * 16, (n0g2 + 64) * 2, lane), bl[8]);
#pragma unroll
        for (int mt = 0; mt < 2; mt++)
#pragma unroll
        for (int nt = 0; nt < 9; nt++) {
            mma_bf16(acc2[mt][nt], ah[mt], bh[nt]);
            mma_bf16(acc2[mt][nt], ah[mt], bl[nt]);
            mma_bf16(acc2[mt][nt], al[mt], bh[nt]);
        }
    }
    __syncthreads();                      // H/W2 regions reusable

    // ============ epilogue 2: V = C2+b2 -> Vs, trace (smem atomics) =========
    {
        float* Vs = reinterpret_cast<float*>(smem + OFF_VS);
        float part[2][2] = {{0.f, 0.f}, {0.f, 0.f}};
#pragma unroll
        for (int mt = 0; mt < 2; mt++)
#pragma unroll
        for (int nt = 0; nt < 9; nt++) {
            int col = n0g2 + nt * 8 + ((lane & 3) << 1);
            if (col < TRIL) {
                float ba = bias2[col];
                float bb = (col + 1 < TRIL) ? bias2[col + 1] : 0.f;
                int r = m0 + mt * 16 + (lane >> 2);
#pragma unroll
                for (int half = 0; half < 2; half++) {
                    float v0 = acc2[mt][nt][2*half] + ba;
                    Vs[(r + half*8) * VS_STRIDE + col] = v0;
                    part[mt][half] = fmaf(v0, v0, part[mt][half]);
                    if (col + 1 < TRIL) {
                        float v1 = acc2[mt][nt][2*half + 1] + bb;
                        Vs[(r + half*8) * VS_STRIDE + col + 1] = v1;
                        part[mt][half] = fmaf(v1, v1, part[mt][half]);
                    }
                }
            }
        }
#pragma unroll
        for (int mt = 0; mt < 2; mt++)
#pragma unroll
        for (int half = 0; half < 2; half++)
            atomicAdd(&trc[m0 + mt * 16 + (lane >> 2) + half * 8], part[mt][half]);
    }
    __syncthreads();

    // ===================== stage 3: rho = L L^T / trace =====================
    {
        const float* Vs = reinterpret_cast<const float*>(smem + OFF_VS);
        const int row = tid & 127;
        const int ib  = tid >> 7;
        const float* vrow = &Vs[row * VS_STRIDE];
        const float invtr = 1.0f / trc[row];
        float* orow = &out[(size_t)(brow + row) * 256];
        if (ib == 0) {
            rho_row<0>(vrow, invtr, orow);  rho_row<2>(vrow, invtr, orow);
            rho_row<4>(vrow, invtr, orow);  rho_row<6>(vrow, invtr, orow);
            rho_row<8>(vrow, invtr, orow);  rho_row<10>(vrow, invtr, orow);
            rho_row<12>(vrow, invtr, orow); rho_row<14>(vrow, invtr, orow);
        } else {
            rho_row<1>(vrow, invtr, orow);  rho_row<3>(vrow, invtr, orow);
            rho_row<5>(vrow, invtr, orow);  rho_row<7>(vrow, invtr, orow);
            rho_row<9>(vrow, invtr, orow);  rho_row<11>(vrow, invtr, orow);
            rho_row<13>(vrow, invtr, orow); rho_row<15>(vrow, invtr, orow);
        }
    }
}

extern "C" void kernel_launch(void* const* d_in, const int* in_sizes, int n_in,
                              void* d_out, int out_size) {
    const float* x  = (const float*)d_in[0];
    const float* W1 = (const float*)d_in[1];
    const float* b1 = (const float*)d_in[2];
    const float* W2 = (const float*)d_in[3];
    const float* b2 = (const float*)d_in[4];
    float* out = (float*)d_out;

    const int batch  = in_sizes[0] / 256;   // 131072
    const int blocks = batch / 128;         // 1024

    cudaFuncSetAttribute(density_mlp_hmma,
                         cudaFuncAttributeMaxDynamicSharedMemorySize, SMEM_BYTES);
    density_mlp_hmma<<<blocks, THREADS, SMEM_BYTES>>>(x, W1, b1, W2, b2, out);
}